// round 9
// baseline (speedup 1.0000x reference)
#include <cuda_runtime.h>

#define SIGMA 10.0f
#define RHO   28.0f
#define BETA  (8.0f / 3.0f)
#define DT    0.01f
#define TSTEPS 64

using u64 = unsigned long long;

// ---- packed f32x2 primitives (Blackwell FFMA2 path) ----
__device__ __forceinline__ u64 f2fma(u64 a, u64 b, u64 c) {
    u64 d; asm("fma.rn.f32x2 %0, %1, %2, %3;" : "=l"(d) : "l"(a), "l"(b), "l"(c)); return d;
}
__device__ __forceinline__ u64 f2add(u64 a, u64 b) {
    u64 d; asm("add.rn.f32x2 %0, %1, %2;" : "=l"(d) : "l"(a), "l"(b)); return d;
}
__device__ __forceinline__ u64 f2mul(u64 a, u64 b) {
    u64 d; asm("mul.rn.f32x2 %0, %1, %2;" : "=l"(d) : "l"(a), "l"(b)); return d;
}
__device__ __forceinline__ u64 pk2(float f) {
    unsigned u = __float_as_uint(f);
    return (u64)u * 0x0000000100000001ULL;
}
// a - b via fma(b, -1, a): stays on fma pipe
__device__ __forceinline__ u64 f2sub(u64 a, u64 b, u64 NEG1) { return f2fma(b, NEG1, a); }

__global__ void __launch_bounds__(32)
lya_spec_kernel(const float* __restrict__ x_in,
                const float* __restrict__ tseq,
                float* __restrict__ out,
                int B, int T, int write_xf)
{
    int i = blockIdx.x * blockDim.x + threadIdx.x;   // pair index
    int B2 = B >> 1;
    if (i >= B2) return;

    // ---- constants ----
    const float a_f    = 1.0f - DT * SIGMA;          // 0.9
    const float s_f    = DT * SIGMA;                 // 0.1
    const float d00_f  = a_f * a_f + s_f * s_f;      // 0.82
    const float q_f    = 1.0f - DT;                  // 0.99
    const float bdt_f  = 1.0f - BETA * DT;
    const float rs_f   = rsqrtf(d00_f);              // 1/sqrt(d00)

    const u64 NEG1    = pk2(-1.0f);
    const u64 C_NRHO  = pk2(-RHO);
    const u64 C_NIB   = pk2(-1.0f / BETA);           // -1/beta
    const u64 C_NHDT  = pk2(-0.5f * DT);
    const u64 C_NBH   = pk2(-BETA * 0.5f * DT);      // -beta*h
    const u64 C_NBDT  = pk2(-BETA * DT);             // -beta*dt
    const u64 C_NDT   = pk2(-DT);
    const u64 C_TWO   = pk2(2.0f);
    const u64 C_NDT6  = pk2(-DT / 6.0f);
    const u64 C_NBD6  = pk2(-BETA * DT / 6.0f);
    const u64 C_HS    = pk2(0.5f * DT * SIGMA);      // h*sigma
    const u64 C_DS    = pk2(DT * SIGMA);             // dt*sigma
    const u64 C_SD6   = pk2(DT * SIGMA / 6.0f);      // dt*sigma/6
    const u64 C_RHODT = pk2(RHO * DT);
    const u64 C_DTOB  = pk2(DT / BETA);              // dt/beta (w10 from W)
    const u64 C_E1    = pk2(s_f * rs_f);             // s/sqrt(d00)
    const u64 C_E0    = pk2(-a_f * q_f * rs_f);      // -a*q/sqrt(d00)
    const u64 C_DT2   = pk2(DT * DT);
    const u64 C_ADT2  = pk2(a_f * DT * DT);
    const u64 C_NSB   = pk2(-s_f * bdt_f);
    const u64 C_NSDT2 = pk2(-s_f * DT * DT);
    const u64 C_AQB   = pk2(a_f * q_f * bdt_f);      // const part of det
    const u64 ONE     = pk2(1.0f);
    const u64 C_NB    = pk2(-BETA);

    // load 2 adjacent trajectories packed
    const u64* xr = (const u64*)x_in;
    int rb = B2;
    u64 X = xr[i];
    u64 Y = xr[rb + i];
    u64 W = f2mul(xr[2 * rb + i], C_NB);   // W = -beta * z

    // split accumulators: independent mul chains, merged at the end
    u64 P1a = ONE, P1b = ONE;
    u64 Pda = ONE, Pdb = ONE;

    #pragma unroll 4
    for (int s = 0; s < TSTEPS; ++s) {
        // ---------- RK4 in (X, Y, W=-beta*z) space ----------
        u64 sx1  = f2sub(Y, X, NEG1);
        u64 nw   = f2fma(W, C_NIB, C_NRHO);          // z - rho
        u64 nk1y = f2fma(X, nw, Y);                  // -(x(rho-z)-y)
        u64 k1z  = f2fma(X, Y, W);                   // xy - beta*z

        u64 ax = f2fma(C_HS,   sx1,  X);
        u64 ay = f2fma(C_NHDT, nk1y, Y);
        u64 aw = f2fma(k1z, C_NBH, W);
        u64 sx2  = f2sub(ay, ax, NEG1);
        nw       = f2fma(aw, C_NIB, C_NRHO);
        u64 nk2y = f2fma(ax, nw, ay);
        u64 k2z  = f2fma(ax, ay, aw);

        ax = f2fma(C_HS,   sx2,  X);
        ay = f2fma(C_NHDT, nk2y, Y);
        aw = f2fma(k2z, C_NBH, W);
        u64 sx3  = f2sub(ay, ax, NEG1);
        nw       = f2fma(aw, C_NIB, C_NRHO);
        u64 nk3y = f2fma(ax, nw, ay);
        u64 k3z  = f2fma(ax, ay, aw);

        // k4 at x + dt*k2 (faithful to reference bug)
        ax = f2fma(C_DS,  sx2,  X);
        ay = f2fma(C_NDT, nk2y, Y);
        aw = f2fma(k2z, C_NBDT, W);
        u64 sx4  = f2sub(ay, ax, NEG1);
        nw       = f2fma(aw, C_NIB, C_NRHO);
        u64 nk4y = f2fma(ax, nw, ay);
        u64 k4z  = f2fma(ax, ay, aw);

        X = f2fma(C_SD6,  f2fma(C_TWO, f2add(sx2,  sx3),  f2add(sx1,  sx4)),  X);
        Y = f2fma(C_NDT6, f2fma(C_TWO, f2add(nk2y, nk3y), f2add(nk1y, nk4y)), Y);
        W = f2fma(C_NBD6, f2fma(C_TWO, f2add(k2z,  k3z),  f2add(k1z,  k4z)),  W);

        // ---------- Gram row-1 (closed form) + det(P), dt^2 folded into consts ----------
        u64 w10 = f2fma(W, C_DTOB, C_RHODT);         // dt*(rho - z)
        u64 X2  = f2mul(X, X);
        u64 XY  = f2mul(X, Y);

        u64 e   = f2fma(w10, C_E1, C_E0);            // (s*w10 - a*q)/sqrt(d00)
        u64 ee  = f2mul(e, e);
        u64 d11 = f2fma(X2, C_DT2, ee);              // dt^2 x^2 + e^2

        u64 t1  = f2fma(X2, C_ADT2, C_AQB);
        u64 t2  = f2fma(w10, C_NSB, t1);
        u64 det = f2fma(XY, C_NSDT2, t2);            // det(P) > 0 on attractor

        if (s & 1) { P1b = f2mul(P1b, d11); Pdb = f2mul(Pdb, det); }
        else       { P1a = f2mul(P1a, d11); Pda = f2mul(Pda, det); }
    }

    u64 P1 = f2mul(P1a, P1b);
    u64 Pd = f2mul(Pda, Pdb);

    // lya0 = const;  lya1 = sc*log(P1);  lya2 = sc*(2*log(Pd) - N*log(d00) - log(P1))
    float tl = tseq[T - 1];
    float sc = __fdividef(0.5f, tl + DT);
    float ld00N = (float)TSTEPS * __logf(d00_f);
    float ly0 = sc * ld00N;

    float2* o2 = (float2*)out;
    o2[i] = make_float2(ly0, ly0);

    float lp1_lo = __logf(__uint_as_float((unsigned)P1));
    float lp1_hi = __logf(__uint_as_float((unsigned)(P1 >> 32)));
    o2[rb + i] = make_float2(sc * lp1_lo, sc * lp1_hi);

    float lpd_lo = __logf(__uint_as_float((unsigned)Pd));
    float lpd_hi = __logf(__uint_as_float((unsigned)(Pd >> 32)));
    o2[2 * rb + i] = make_float2(sc * (2.0f * lpd_lo - ld00N - lp1_lo),
                                 sc * (2.0f * lpd_hi - ld00N - lp1_hi));

    if (write_xf) {
        u64* o8 = (u64*)out;
        o8[3 * rb + i] = X;
        o8[4 * rb + i] = Y;
        o8[5 * rb + i] = f2mul(W, C_NIB);   // z = -W/beta
    }
}

extern "C" void kernel_launch(void* const* d_in, const int* in_sizes, int n_in,
                              void* d_out, int out_size) {
    const float* x    = (const float*)d_in[0];
    const float* tseq = (const float*)d_in[1];
    float* out = (float*)d_out;

    int B = in_sizes[0] / 3;          // x is [3, B]
    int T = in_sizes[1];
    int write_xf = (out_size >= 6 * B) ? 1 : 0;

    int B2 = B >> 1;                  // 2 trajectories per thread
    int threads = 32;                 // 1-warp blocks: finest wave-balance granularity
    int blocks = (B2 + threads - 1) / threads;
    lya_spec_kernel<<<blocks, threads>>>(x, tseq, out, B, T, write_xf);
}

// round 10
// speedup vs baseline: 1.0837x; 1.0837x over previous
#include <cuda_runtime.h>

#define SIGMA 10.0f
#define RHO   28.0f
#define BETA  (8.0f / 3.0f)
#define DT    0.01f
#define TSTEPS 64

using u64 = unsigned long long;

// ---- packed f32x2 primitives (Blackwell FFMA2 path) ----
__device__ __forceinline__ u64 f2fma(u64 a, u64 b, u64 c) {
    u64 d; asm("fma.rn.f32x2 %0, %1, %2, %3;" : "=l"(d) : "l"(a), "l"(b), "l"(c)); return d;
}
__device__ __forceinline__ u64 f2add(u64 a, u64 b) {
    u64 d; asm("add.rn.f32x2 %0, %1, %2;" : "=l"(d) : "l"(a), "l"(b)); return d;
}
__device__ __forceinline__ u64 f2mul(u64 a, u64 b) {
    u64 d; asm("mul.rn.f32x2 %0, %1, %2;" : "=l"(d) : "l"(a), "l"(b)); return d;
}
__device__ __forceinline__ u64 pk2(float f) {
    unsigned u = __float_as_uint(f);
    return (u64)u * 0x0000000100000001ULL;
}
// a - b via fma(b, -1, a): stays on fma pipe
__device__ __forceinline__ u64 f2sub(u64 a, u64 b, u64 NEG1) { return f2fma(b, NEG1, a); }

__global__ void __launch_bounds__(32)
lya_spec_kernel(const float* __restrict__ x_in,
                const float* __restrict__ tseq,
                float* __restrict__ out,
                int B, int T, int write_xf)
{
    int i = blockIdx.x * blockDim.x + threadIdx.x;   // pair index
    int B2 = B >> 1;
    if (i >= B2) return;

    // ---- constants ----
    const float a_f    = 1.0f - DT * SIGMA;          // 0.9
    const float s_f    = DT * SIGMA;                 // 0.1
    const float d00_f  = a_f * a_f + s_f * s_f;      // 0.82
    const float q_f    = 1.0f - DT;                  // 0.99
    const float bdt_f  = 1.0f - BETA * DT;
    const float rs_f   = rsqrtf(d00_f);              // 1/sqrt(d00)

    const u64 NEG1    = pk2(-1.0f);
    const u64 C_NRHO  = pk2(-RHO);
    const u64 C_NIB   = pk2(-1.0f / BETA);           // -1/beta
    const u64 C_NHDT  = pk2(-0.5f * DT);
    const u64 C_NBH   = pk2(-BETA * 0.5f * DT);      // -beta*h
    const u64 C_NBDT  = pk2(-BETA * DT);             // -beta*dt
    const u64 C_NDT   = pk2(-DT);
    const u64 C_TWO   = pk2(2.0f);
    const u64 C_NDT6  = pk2(-DT / 6.0f);
    const u64 C_NBD6  = pk2(-BETA * DT / 6.0f);
    const u64 C_HS    = pk2(0.5f * DT * SIGMA);      // h*sigma
    const u64 C_DS    = pk2(DT * SIGMA);             // dt*sigma
    const u64 C_SD6   = pk2(DT * SIGMA / 6.0f);      // dt*sigma/6
    // tail constants expressed in nw = z - rho (w10 = -dt*nw folded in)
    const u64 C_E1N   = pk2(-DT * s_f * rs_f);       // e = C_E1N*nw + C_E0
    const u64 C_E0    = pk2(-a_f * q_f * rs_f);
    const u64 C_DT2   = pk2(DT * DT);
    const u64 C_ADT2  = pk2(a_f * DT * DT);
    const u64 C_SBDT  = pk2(s_f * bdt_f * DT);       // det: +s*bdt*dt*nw
    const u64 C_NSDT2 = pk2(-s_f * DT * DT);
    const u64 C_AQB   = pk2(a_f * q_f * bdt_f);      // const part of det
    const u64 ONE     = pk2(1.0f);
    const u64 C_NB    = pk2(-BETA);

    // load 2 adjacent trajectories packed
    const u64* xr = (const u64*)x_in;
    int rb = B2;
    u64 X = xr[i];
    u64 Y = xr[rb + i];
    u64 W = f2mul(xr[2 * rb + i], C_NB);   // W = -beta * z
    u64 nw = f2fma(W, C_NIB, C_NRHO);      // z - rho (carried across iterations)

    // split accumulators: independent mul chains, merged at the end
    u64 P1a = ONE, P1b = ONE;
    u64 Pda = ONE, Pdb = ONE;

    #pragma unroll 4
    for (int s = 0; s < TSTEPS; ++s) {
        // ---------- RK4 in (X, Y, W=-beta*z) space; nw carried in ----------
        u64 sx1  = f2sub(Y, X, NEG1);
        u64 nk1y = f2fma(X, nw, Y);                  // -(x(rho-z)-y)
        u64 k1z  = f2fma(X, Y, W);                   // xy - beta*z

        u64 ax = f2fma(C_HS,   sx1,  X);
        u64 ay = f2fma(C_NHDT, nk1y, Y);
        u64 aw = f2fma(k1z, C_NBH, W);
        u64 sx2  = f2sub(ay, ax, NEG1);
        u64 anw  = f2fma(aw, C_NIB, C_NRHO);
        u64 nk2y = f2fma(ax, anw, ay);
        u64 k2z  = f2fma(ax, ay, aw);

        ax = f2fma(C_HS,   sx2,  X);
        ay = f2fma(C_NHDT, nk2y, Y);
        aw = f2fma(k2z, C_NBH, W);
        u64 sx3  = f2sub(ay, ax, NEG1);
        anw      = f2fma(aw, C_NIB, C_NRHO);
        u64 nk3y = f2fma(ax, anw, ay);
        u64 k3z  = f2fma(ax, ay, aw);

        // k4 at x + dt*k2 (faithful to reference bug)
        ax = f2fma(C_DS,  sx2,  X);
        ay = f2fma(C_NDT, nk2y, Y);
        aw = f2fma(k2z, C_NBDT, W);
        u64 sx4  = f2sub(ay, ax, NEG1);
        anw      = f2fma(aw, C_NIB, C_NRHO);
        u64 nk4y = f2fma(ax, anw, ay);
        u64 k4z  = f2fma(ax, ay, aw);

        X = f2fma(C_SD6,  f2fma(C_TWO, f2add(sx2,  sx3),  f2add(sx1,  sx4)),  X);
        Y = f2fma(C_NDT6, f2fma(C_TWO, f2add(nk2y, nk3y), f2add(nk1y, nk4y)), Y);
        W = f2fma(C_NBD6, f2fma(C_TWO, f2add(k2z,  k3z),  f2add(k1z,  k4z)),  W);

        // ---------- Gram row-1 (closed form) + det(P), in nw-space ----------
        nw = f2fma(W, C_NIB, C_NRHO);                // z - rho (feeds tail AND next k1)
        u64 X2  = f2mul(X, X);
        u64 XY  = f2mul(X, Y);

        u64 e   = f2fma(nw, C_E1N, C_E0);            // (s*w10 - a*q)/sqrt(d00)
        u64 ee  = f2mul(e, e);
        u64 d11 = f2fma(X2, C_DT2, ee);              // dt^2 x^2 + e^2

        u64 t1  = f2fma(X2, C_ADT2, C_AQB);
        u64 t2  = f2fma(nw, C_SBDT, t1);
        u64 det = f2fma(XY, C_NSDT2, t2);            // det(P) > 0 on attractor

        if (s & 1) { P1b = f2mul(P1b, d11); Pdb = f2mul(Pdb, det); }
        else       { P1a = f2mul(P1a, d11); Pda = f2mul(Pda, det); }
    }

    u64 P1 = f2mul(P1a, P1b);
    u64 Pd = f2mul(Pda, Pdb);

    // lya0 = const;  lya1 = sc*log(P1);  lya2 = sc*(2*log(Pd) - N*log(d00) - log(P1))
    float tl = tseq[T - 1];
    float sc = __fdividef(0.5f, tl + DT);
    float ld00N = (float)TSTEPS * __logf(d00_f);
    float ly0 = sc * ld00N;

    float2* o2 = (float2*)out;
    o2[i] = make_float2(ly0, ly0);

    float lp1_lo = __logf(__uint_as_float((unsigned)P1));
    float lp1_hi = __logf(__uint_as_float((unsigned)(P1 >> 32)));
    o2[rb + i] = make_float2(sc * lp1_lo, sc * lp1_hi);

    float lpd_lo = __logf(__uint_as_float((unsigned)Pd));
    float lpd_hi = __logf(__uint_as_float((unsigned)(Pd >> 32)));
    o2[2 * rb + i] = make_float2(sc * (2.0f * lpd_lo - ld00N - lp1_lo),
                                 sc * (2.0f * lpd_hi - ld00N - lp1_hi));

    if (write_xf) {
        u64* o8 = (u64*)out;
        o8[3 * rb + i] = X;
        o8[4 * rb + i] = Y;
        o8[5 * rb + i] = f2mul(W, C_NIB);   // z = -W/beta
    }
}

extern "C" void kernel_launch(void* const* d_in, const int* in_sizes, int n_in,
                              void* d_out, int out_size) {
    const float* x    = (const float*)d_in[0];
    const float* tseq = (const float*)d_in[1];
    float* out = (float*)d_out;

    int B = in_sizes[0] / 3;          // x is [3, B]
    int T = in_sizes[1];
    int write_xf = (out_size >= 6 * B) ? 1 : 0;

    int B2 = B >> 1;                  // 2 trajectories per thread
    int threads = 32;                 // 1-warp blocks: finest wave-balance granularity
    int blocks = (B2 + threads - 1) / threads;
    lya_spec_kernel<<<blocks, threads>>>(x, tseq, out, B, T, write_xf);
}